// round 9
// baseline (speedup 1.0000x reference)
#include <cuda_runtime.h>

#define BB 16
#define TT 96
#define TP1 97
#define HW 16384
#define NSTEP 6
#define MTHR 0.9f
#define NBLK 512            // persistent step-kernel blocks (co-resident)
#define PXB 512             // pixels owned per step-block

// ---- scratch (device globals; no allocation APIs) ----
__device__ float         g_D[(size_t)BB * HW * TT];  // d[b][p][t], t contiguous (~100MB)
__device__ double        g_delta[BB * TP1];          // idx0 = empty template, always 0
__device__ unsigned char g_topcov[BB * HW];
__device__ float         g_topval[BB * HW];
__device__ int           g_bcnt[8];                  // barrier arrival counters (self-resetting)
__device__ int           g_bgen[8];                  // barrier generations (monotonic)

// ---------------------------------------------------------------------------
__global__ void k_init() {
    int i = threadIdx.x;
    for (int j = i; j < BB * TP1; j += 256) g_delta[j] = 0.0;
}

// ---------------------------------------------------------------------------
// Phase A: precompute D[b][p][t] = cov ? (x-t*m)^2 - (x-bg)^2 : 0 and delta0.
// One 64-pixel tile per block; 6 blocks/SM (42-reg budget, 25.5KB smem).
// delta0 tile-sums via 16-lane shuffle reduction -> 1 fp64 atomic per (tile,t).
__global__ void __launch_bounds__(256, 6)
k_pre(const float* __restrict__ x,
      const float* __restrict__ temps,
      const float* __restrict__ msks,
      const float* __restrict__ bg) {
    __shared__ float xs[64], eb[64];
    __shared__ float dsm[64][TP1];   // stride 97: conflict-free transpose

    const int b   = blockIdx.y;
    const int p0  = blockIdx.x * 64;
    const int tid = threadIdx.x;

    if (tid < 64) {
        float xv = x[b * HW + p0 + tid];
        float bv = bg[p0 + tid];
        xs[tid] = xv;
        float e = xv - bv;
        eb[tid] = e * e;
        g_topcov[b * HW + p0 + tid] = 0;
    }
    __syncthreads();

    const int ts  = tid >> 4;        // 16 templates per iteration
    const int ps4 = tid & 15;        // float4 pixel group (lanes sharing t are
                                     // a contiguous aligned 16-lane group)
    #pragma unroll
    for (int t16 = 0; t16 < TT; t16 += 16) {
        int t = t16 + ts;
        const size_t rb = (size_t)(b * TT + t) * HW + p0;
        float4 tv = __ldg((const float4*)(temps + rb) + ps4);
        float4 mv = __ldg((const float4*)(msks  + rb) + ps4);
        int p = 4 * ps4;
        float d0 = 0.f, d1 = 0.f, d2 = 0.f, d3 = 0.f;
        if (mv.x > MTHR) { float a = xs[p]     - tv.x * mv.x; d0 = a * a - eb[p];     }
        if (mv.y > MTHR) { float a = xs[p + 1] - tv.y * mv.y; d1 = a * a - eb[p + 1]; }
        if (mv.z > MTHR) { float a = xs[p + 2] - tv.z * mv.z; d2 = a * a - eb[p + 2]; }
        if (mv.w > MTHR) { float a = xs[p + 3] - tv.w * mv.w; d3 = a * a - eb[p + 3]; }
        dsm[p][t]     = d0;
        dsm[p + 1][t] = d1;
        dsm[p + 2][t] = d2;
        dsm[p + 3][t] = d3;
        // tile-sum for template t across its 16 lanes (64 pixels)
        float v = (d0 + d1) + (d2 + d3);
        v += __shfl_xor_sync(0xffffffffu, v, 1);
        v += __shfl_xor_sync(0xffffffffu, v, 2);
        v += __shfl_xor_sync(0xffffffffu, v, 4);
        v += __shfl_xor_sync(0xffffffffu, v, 8);
        if (ps4 == 0) atomicAdd(&g_delta[b * TP1 + 1 + t], (double)v);
    }
    __syncthreads();

    // store D t-contiguous: global index (b*HW+p0)*96 + i contiguous in i
    const size_t obase = ((size_t)b * HW + p0) * TT;
    for (int i = tid; i < 64 * TT / 4; i += 256) {
        int r = i / 24, c = (i % 24) * 4;
        float4 v4 = make_float4(dsm[r][c], dsm[r][c + 1], dsm[r][c + 2], dsm[r][c + 3]);
        *(float4*)&g_D[obase + (size_t)i * 4] = v4;
    }
}

// ---------------------------------------------------------------------------
// Grid-wide sense-reversing barrier; gen is monotonic (graph-replay safe).
// All NBLK blocks co-resident (tiny smem/regs: trivially satisfied).
__device__ __forceinline__ void grid_barrier(int slot) {
    __syncthreads();
    __threadfence();
    if (threadIdx.x == 0) {
        int g   = atomicAdd(&g_bgen[slot], 0);
        int old = atomicAdd(&g_bcnt[slot], 1);
        if (old == NBLK - 1) {
            g_bcnt[slot] = 0;
            __threadfence();
            atomicExch(&g_bgen[slot], g + 1);
        } else {
            while (atomicAdd(&g_bgen[slot], 0) == g) __nanosleep(64);
        }
    }
    __syncthreads();
    __threadfence();
}

// ---------------------------------------------------------------------------
// Phase B: persistent greedy steps. Block owns 512 pixels of one batch.
__global__ void __launch_bounds__(256)
k_steps(const float* __restrict__ temps,
        const float* __restrict__ msks,
        const float* __restrict__ bg,
        float* __restrict__ out) {
    __shared__ int      list[PXB];
    __shared__ float    partial[2][TT];
    __shared__ unsigned wm[8];
    __shared__ int      scid;
    __shared__ unsigned char used[TP1];

    const int tid = threadIdx.x;
    const int blk = blockIdx.x;
    const int b   = blk >> 5;            // 32 blocks per batch
    const int p0g = (blk & 31) * PXB;

    if (tid < TP1) used[tid] = 0;
    __syncthreads();

    for (int s = 0; s < NSTEP; s++) {
        // --- argmin over 97 candidates (redundant per block, identical) ---
        if (tid < 32) {
            double bestv = 1e300;
            int    besti = TP1;
            for (int t = tid; t < TP1; t += 32) {
                double v = __ldcg(&g_delta[b * TP1 + t]);
                if (used[t]) v = 1e30;
                if (v < bestv) { bestv = v; besti = t; }   // earliest on tie
            }
            for (int off = 16; off; off >>= 1) {
                double ov = __shfl_down_sync(0xffffffffu, bestv, off);
                int    oi = __shfl_down_sync(0xffffffffu, besti, off);
                if (ov < bestv || (ov == bestv && oi < besti)) { bestv = ov; besti = oi; }
            }
            if (tid == 0) {
                scid = besti;
                if (besti != 0) used[besti] = 1;
            }
        }
        __syncthreads();
        const int cid = scid;

        // --- paint own pixels + deterministic compaction of new ones ---
        int base = 0;
        if (cid != 0) {
            const size_t mrow = (size_t)(b * TT + cid - 1) * HW;
            #pragma unroll
            for (int k = 0; k < PXB / 256; k++) {
                int lp = k * 256 + tid;
                int p  = p0g + lp;
                int q  = b * HW + p;
                bool nw = false;
                float mv = msks[mrow + p];
                if (mv > MTHR && !g_topcov[q]) {
                    g_topval[q] = temps[mrow + p] * mv;  // goes UNDER existing
                    g_topcov[q] = 1;
                    nw = true;
                }
                unsigned m = __ballot_sync(0xffffffffu, nw);
                if ((tid & 31) == 0) wm[tid >> 5] = m;
                __syncthreads();
                int off = base, tot = 0;
                #pragma unroll
                for (int w = 0; w < 8; w++) {
                    int c = __popc(wm[w]);
                    if (w < (tid >> 5)) off += c;
                    tot += c;
                }
                if (nw) list[off + __popc(m & ((1u << (tid & 31)) - 1))] = lp;
                base += tot;
                __syncthreads();
            }
        }
        const int n = base;

        if (s == NSTEP - 1) {
            // --- final composition for own pixels ---
            #pragma unroll
            for (int k = 0; k < PXB / 256; k++) {
                int p = p0g + k * 256 + tid;
                int q = b * HW + p;
                out[q] = g_topcov[q] ? g_topval[q] : bg[p];
            }
        } else {
            // --- gather-subtract D rows of own new pixels ---
            if (n > 0) {
                const int grp = tid >> 7;    // 0/1: even/odd list entries
                const int lt  = tid & 127;
                float a0 = 0.f, a1 = 0.f, a2 = 0.f, a3 = 0.f;
                if (lt < TT) {
                    const float* Db = g_D + ((size_t)b * HW + p0g) * TT + lt;
                    int j = grp;
                    for (; j + 6 < n; j += 8) {
                        a0 += Db[(size_t)list[j    ] * TT];
                        a1 += Db[(size_t)list[j + 2] * TT];
                        a2 += Db[(size_t)list[j + 4] * TT];
                        a3 += Db[(size_t)list[j + 6] * TT];
                    }
                    for (; j < n; j += 2) a0 += Db[(size_t)list[j] * TT];
                    partial[grp][lt] = (a0 + a1) + (a2 + a3);
                }
                __syncthreads();
                if (tid < TT) {
                    float tot2 = partial[0][tid] + partial[1][tid];
                    atomicAdd(&g_delta[b * TP1 + 1 + tid], -(double)tot2);
                }
            }
            grid_barrier(s);
        }
    }
}

// ---------------------------------------------------------------------------
extern "C" void kernel_launch(void* const* d_in, const int* in_sizes, int n_in,
                              void* d_out, int out_size) {
    const float* x      = (const float*)d_in[0];   // (16,1,128,128)
    const float* temps  = (const float*)d_in[1];   // (16,96,1,128,128)
    const float* msks   = (const float*)d_in[2];   // (16,96,1,128,128)
    const float* bg     = (const float*)d_in[3];   // (1,128,128)
    float* out = (float*)d_out;                    // (16,1,128,128)

    k_init<<<1, 256>>>();
    k_pre<<<dim3(HW / 64, BB), 256>>>(x, temps, msks, bg);
    k_steps<<<NBLK, 256>>>(temps, msks, bg, out);
}